// round 16
// baseline (speedup 1.0000x reference)
#include <cuda_runtime.h>
#include <cuda_bf16.h>
#include <cstdint>
#include <math.h>

#define BB 64
#define TT 512
#define DD 1024
#define HH 1024
#define SIXH (6 * HH)
#define FIVEH (5 * HH)
#define BTH (BB * TT * HH)
#define BH (BB * HH)

#define NBLK 128

// input-projection GEMM (unchanged)
#define GK 3072
#define GKC 64
#define GNCHUNK (GK / GKC)
#define GMT 128
#define GNT 256
#define GSTAGE 49152
#define SMEM_GEMM (2 * GSTAGE)

// recurrent kernel: W resident (160KB); A ring 8 chunks x 8KB = 64KB.
// ps (4 k-parts) / hstg / ystg overlay the A ring (used only after chunk loop).
#define ASTG 8192
#define WSM 163840
#define A_OFF WSM
#define PS_PAD 42
#define HSTG_OFF (A_OFF + 4 * 64 * PS_PAD * 4)   // A_OFF + 43008
#define YSTG_OFF (HSTG_OFF + 2048)
#define SMEM_REC (WSM + 8 * ASTG)                // 229376 (224KB)

__device__ __align__(16) float g_pi[201326592];
__device__ __align__(16) float g_y0[BTH];
__device__ __align__(16) __nv_bfloat16 g_Abf[98304ull * 1024ull];
__device__ __align__(16) __nv_bfloat16 g_Bbf[6144ull * 3072ull];
__device__ __align__(128) __nv_bfloat16 g_Wr[128ull * 32ull * 2560ull];
__device__ __align__(128) __nv_bfloat16 g_Ah[2][131072];

// hierarchical grid barrier state (monotonic counters; replay-safe)
__device__ unsigned g_cnt[8];
__device__ unsigned g_cntm;
__device__ unsigned g_rel;

__device__ __forceinline__ float sigf(float x) { return 1.f / (1.f + expf(-x)); }

__device__ __forceinline__ uint32_t smem_u32(const void* p) {
    uint32_t a;
    asm("{ .reg .u64 t; cvta.to.shared.u64 t, %1; cvt.u32.u64 %0, t; }" : "=r"(a) : "l"(p));
    return a;
}
__device__ __forceinline__ void cp_async16(uint32_t d, const void* g) {
    asm volatile("cp.async.cg.shared.global [%0], [%1], 16;" :: "r"(d), "l"(g));
}
__device__ __forceinline__ void ldsm_x4(uint32_t addr, uint32_t& r0, uint32_t& r1,
                                        uint32_t& r2, uint32_t& r3) {
    asm volatile("ldmatrix.sync.aligned.m8n8.x4.shared.b16 {%0,%1,%2,%3}, [%4];"
                 : "=r"(r0), "=r"(r1), "=r"(r2), "=r"(r3) : "r"(addr));
}
__device__ __forceinline__ void ldsm_x2(uint32_t addr, uint32_t& r0, uint32_t& r1) {
    asm volatile("ldmatrix.sync.aligned.m8n8.x2.shared.b16 {%0,%1}, [%2];"
                 : "=r"(r0), "=r"(r1) : "r"(addr));
}
__device__ __forceinline__ void mma16816(float* c, const uint32_t* a, const uint32_t* b) {
    asm volatile("mma.sync.aligned.m16n8k16.row.col.f32.bf16.bf16.f32 "
                 "{%0,%1,%2,%3}, {%4,%5,%6,%7}, {%8,%9}, {%0,%1,%2,%3};"
                 : "+f"(c[0]), "+f"(c[1]), "+f"(c[2]), "+f"(c[3])
                 : "r"(a[0]), "r"(a[1]), "r"(a[2]), "r"(a[3]), "r"(b[0]), "r"(b[1]));
}

// hierarchical epoch barrier: 8 group counters -> master -> release word
__device__ __forceinline__ void grid_barrier(unsigned ep, int jb) {
    __syncthreads();
    if (threadIdx.x == 0) {
        __threadfence();
        unsigned v = atomicAdd(&g_cnt[jb & 7], 1u) + 1u;
        if (v == ep * 16u) {
            unsigned m = atomicAdd(&g_cntm, 1u) + 1u;
            if (m == ep * 8u) {
                atomicExch(&g_rel, ep);
            }
        }
        while (*(volatile unsigned*)&g_rel < ep) { }
    }
    __syncthreads();
}

// ---------------------------------------------------------------------------
__global__ void convA_kernel(const float* __restrict__ src, __nv_bfloat16* __restrict__ dst) {
    size_t i = (size_t)blockIdx.x * blockDim.x + threadIdx.x;
    int m = (int)(i >> 9), r = (int)(i & 511);
    float2 a = ((const float2*)src)[i];
    __nv_bfloat162 hi, lo;
    hi.x = __float2bfloat16(a.x); hi.y = __float2bfloat16(a.y);
    lo.x = __float2bfloat16(a.x - __bfloat162float(hi.x));
    lo.y = __float2bfloat16(a.y - __bfloat162float(hi.y));
    __nv_bfloat162* d = (__nv_bfloat162*)dst + (size_t)m * 1536;
    d[r] = hi; d[512 + r] = lo; d[1024 + r] = hi;
}

__global__ void convB_kernel(const float* __restrict__ W, __nv_bfloat16* __restrict__ dst) {
    __shared__ float t[32][33];
    int nb = blockIdx.x * 32, kb = blockIdx.y * 32;
    int tx = threadIdx.x & 31, ty = threadIdx.x >> 5;
    #pragma unroll
    for (int i = 0; i < 4; i++)
        t[ty + i * 8][tx] = W[(size_t)(kb + ty + i * 8) * SIXH + nb + tx];
    __syncthreads();
    #pragma unroll
    for (int i = 0; i < 4; i++) {
        int ny = ty + i * 8;
        float a = t[tx][ny];
        __nv_bfloat16 hi = __float2bfloat16(a);
        __nv_bfloat16 lo = __float2bfloat16(a - __bfloat162float(hi));
        __nv_bfloat16* dr = dst + (size_t)(nb + ny) * GK;
        dr[kb + tx] = hi; dr[1024 + kb + tx] = hi; dr[2048 + kb + tx] = lo;
    }
}

// ---------------------------------------------------------------------------
__global__ void __launch_bounds__(512, 1) gemm_mma(const __nv_bfloat16* __restrict__ A,
                                                   const __nv_bfloat16* __restrict__ B) {
    extern __shared__ __align__(1024) char sm[];
    const uint32_t sbase = smem_u32(sm);
    const int tid = threadIdx.x, wid = tid >> 5, lane = tid & 31;
    const int n0 = blockIdx.x * GNT, m0 = blockIdx.y * GMT;
    const int m_warp = (wid & 1) * 64;
    const int n_warp = (wid >> 1) * 32;

    const int ahalf = lane >> 4;
    const int bhalf = (lane >> 3) & 1;
    int aoff[4], a7[4], boff[2], b7[2];
    #pragma unroll
    for (int mt = 0; mt < 4; mt++) {
        int r = m_warp + mt * 16 + (lane & 15);
        aoff[mt] = r * 128; a7[mt] = r & 7;
    }
    #pragma unroll
    for (int bt = 0; bt < 2; bt++) {
        int r = n_warp + bt * 16 + (lane & 7) + ((lane >> 4) << 3);
        boff[bt] = r * 128; b7[bt] = r & 7;
    }

    float acc[4][4][4];
    #pragma unroll
    for (int i = 0; i < 4; i++)
        #pragma unroll
        for (int j = 0; j < 4; j++)
            #pragma unroll
            for (int k = 0; k < 4; k++) acc[i][j][k] = 0.f;

    auto load_chunk = [&](int kc, int buf) {
        uint32_t sa = sbase + buf * GSTAGE;
        uint32_t sb = sa + 16384;
        const char* ga = (const char*)(A + (size_t)m0 * GK + kc * GKC);
        const char* gb = (const char*)(B + (size_t)n0 * GK + kc * GKC);
        #pragma unroll
        for (int i = 0; i < 2; i++) {
            int idx = tid + i * 512, r = idx >> 3, c = idx & 7;
            cp_async16(sa + r * 128 + (((c ^ (r & 7)) << 4)), ga + (size_t)r * (GK * 2) + c * 16);
        }
        #pragma unroll
        for (int i = 0; i < 4; i++) {
            int idx = tid + i * 512, r = idx >> 3, c = idx & 7;
            cp_async16(sb + r * 128 + (((c ^ (r & 7)) << 4)), gb + (size_t)r * (GK * 2) + c * 16);
        }
        asm volatile("cp.async.commit_group;" ::: "memory");
    };

    load_chunk(0, 0);
    for (int kc = 0; kc < GNCHUNK; kc++) {
        int buf = kc & 1;
        if (kc + 1 < GNCHUNK) {
            load_chunk(kc + 1, buf ^ 1);
            asm volatile("cp.async.wait_group 1;" ::: "memory");
        } else {
            asm volatile("cp.async.wait_group 0;" ::: "memory");
        }
        __syncthreads();

        uint32_t saA = sbase + buf * GSTAGE;
        uint32_t saB = saA + 16384;
        #pragma unroll
        for (int ks = 0; ks < 4; ks++) {
            uint32_t a[4][4], b[4][2];
            #pragma unroll
            for (int mt = 0; mt < 4; mt++) {
                uint32_t addr = saA + aoff[mt] + ((((ks << 1) + ahalf) ^ a7[mt]) << 4);
                ldsm_x4(addr, a[mt][0], a[mt][1], a[mt][2], a[mt][3]);
            }
            #pragma unroll
            for (int bt = 0; bt < 2; bt++) {
                uint32_t addr = saB + boff[bt] + ((((ks << 1) + bhalf) ^ b7[bt]) << 4);
                ldsm_x4(addr, b[2 * bt][0], b[2 * bt][1], b[2 * bt + 1][0], b[2 * bt + 1][1]);
            }
            #pragma unroll
            for (int mt = 0; mt < 4; mt++)
                #pragma unroll
                for (int nt = 0; nt < 4; nt++)
                    mma16816(acc[mt][nt], a[mt], b[nt]);
        }
        __syncthreads();
    }

    #pragma unroll
    for (int mt = 0; mt < 4; mt++) {
        int m = m0 + m_warp + mt * 16 + (lane >> 2);
        #pragma unroll
        for (int nt = 0; nt < 4; nt++) {
            int n = n0 + n_warp + nt * 8 + (lane & 3) * 2;
            *(float2*)(g_pi + (size_t)m * SIXH + n) = make_float2(acc[mt][nt][0], acc[mt][nt][1]);
            *(float2*)(g_pi + (size_t)(m + 8) * SIXH + n) = make_float2(acc[mt][nt][2], acc[mt][nt][3]);
        }
    }
}

// ---------------------------------------------------------------------------
__global__ void packw_kernel(const float* __restrict__ Ws) {
    size_t idx = (size_t)blockIdx.x * blockDim.x + threadIdx.x;
    if (idx >= 128ull * 32 * 40 * 64) return;
    int kk = (int)(idx & 63); size_t r = idx >> 6;
    int nn = (int)(r % 40); r /= 40;
    int wc = (int)(r & 31); int jb = (int)(r >> 5);
    int g = nn >> 3, jj = jb * 8 + (nn & 7);
    int k = (wc & 15) * 64 + kk;
    float v = Ws[(size_t)k * FIVEH + g * HH + jj];
    __nv_bfloat16 hi = __float2bfloat16(v);
    __nv_bfloat16 o = (wc < 16) ? hi : __float2bfloat16(v - __bfloat162float(hi));
    size_t off = ((size_t)(jb * 32 + wc)) * 2560 + nn * 64 + (((kk >> 3) ^ (nn & 7)) << 3) + (kk & 7);
    g_Wr[off] = o;
}

// ---------------------------------------------------------------------------
// Persistent recurrent kernel: 512 threads, 16 warps = 4 m-tiles x 4 k-quarters.
// W resident in smem. A streamed WARP-AUTONOMOUSLY: each warp cp.asyncs only
// its own 512B slice of each chunk -> warp-local wait + __syncwarp, no
// block-wide syncs inside the chunk loop.
// ---------------------------------------------------------------------------
__global__ void __launch_bounds__(512, 1) rec_kernel(
    const float* __restrict__ bs, const int* __restrict__ lengths,
    float* __restrict__ y, float* __restrict__ outh, float* __restrict__ outc)
{
    extern __shared__ __align__(1024) char sm[];
    __shared__ unsigned s_base;
    const uint32_t sbase = smem_u32(sm);
    float* ps_s = (float*)(sm + A_OFF);                      // 4 x 64 x PS_PAD
    __nv_bfloat16* hstg = (__nv_bfloat16*)(sm + HSTG_OFF);   // [2][64][8]
    float* ystg = (float*)(sm + YSTG_OFF);                    // [64][8]

    const int tid = threadIdx.x, wid = tid >> 5, lane = tid & 31;
    const int jb = blockIdx.x;
    const int mt = wid & 3, kq = wid >> 2;      // m-tile, k-quarter
    const int wg = wid & 7;                     // gate-phase column (wid<8 only)
    const int j = jb * 8 + wg;
    const int r0 = lane, r1 = lane + 32;
    const int cj = jb >> 3, kxor = jb & 7;

    const char* Wbase = (const char*)(g_Wr + (size_t)jb * 32 * 2560);

    if (tid == 0) s_base = *(volatile unsigned*)&g_rel;

    // resident W load: 160KB via cp.async from all threads
    #pragma unroll 4
    for (int i = 0; i < 20; i++) {
        int u = tid + i * 512;
        cp_async16(sbase + u * 16, Wbase + (size_t)u * 16);
    }
    asm volatile("cp.async.commit_group;" ::: "memory");

    // zero A' buffer 0 (initial h = 0): 16384 uint4 over 128 blocks
    if (tid < 128) ((uint4*)g_Ah)[jb * 128 + tid] = make_uint4(0, 0, 0, 0);

    const int len0 = lengths[r0], len1 = lengths[r1];
    float bias[5];
    #pragma unroll
    for (int g = 0; g < 5; g++) bias[g] = (wid < 8) ? bs[g * HH + j] : 0.f;

    asm volatile("cp.async.wait_group 0;" ::: "memory");
    __syncthreads();
    unsigned ep = s_base;
    grid_barrier(++ep, jb);

    const int sw = lane & 7;
    const uint32_t aRow = (uint32_t)((mt * 16 + (lane & 15)) * 128);
    const int ah = lane >> 4;
    const uint32_t bRow0 = (uint32_t)((((lane & 7) + ((lane >> 4) << 3))) * 128);
    const uint32_t bRow1 = bRow0 + 16 * 128;
    const uint32_t bRow2 = (uint32_t)((32 + (lane & 7)) * 128);
    const int bh = (lane >> 3) & 1;
    const int gg = kq * 2;                      // this warp's k16 segment
    const uint32_t aCol = (uint32_t)(((gg + ah) ^ sw) << 4);
    const uint32_t gbCol = (uint32_t)(((gg + bh) ^ sw) << 4);

    // per-lane slice of each A chunk this warp consumes:
    // row rA = mt*16 + (lane>>1); 16B unit uA = (gg ^ (rA&7)) ^ (lane&1)
    const int rA = mt * 16 + (lane >> 1);
    const uint32_t laneOff = (uint32_t)(rA * 128 + (((gg ^ (rA & 7)) ^ (lane & 1)) << 4));
    const uint32_t adst = sbase + A_OFF + laneOff;

    float h0 = 0.f, h1 = 0.f, c0 = 0.f, c1 = 0.f;

    for (int t = 0; t < TT; t++) {
        const char* Asrc = (const char*)(g_Ah[t & 1]) + laneOff;

        // warp-autonomous chunk stream: one 16B per lane per chunk; always commit
        auto issueC = [&](int c) {
            if (c < 32) cp_async16(adst + (uint32_t)((c & 7) * ASTG), Asrc + (size_t)c * ASTG);
            asm volatile("cp.async.commit_group;" ::: "memory");
        };
        issueC(0); issueC(1); issueC(2); issueC(3); issueC(4); issueC(5);

        float p0[6], p1[6];
        if (wid < 8) {
            const float* pr0 = g_pi + ((size_t)r0 * TT + t) * SIXH + j;
            const float* pr1 = g_pi + ((size_t)r1 * TT + t) * SIXH + j;
            #pragma unroll
            for (int g = 0; g < 6; g++) { p0[g] = pr0[g * HH]; p1[g] = pr1[g * HH]; }
        }

        float acc[5][4];
        #pragma unroll
        for (int g = 0; g < 5; g++)
            #pragma unroll
            for (int q = 0; q < 4; q++) acc[g][q] = 0.f;

        // hi phase: chunks 0..15 (A-hi), both W slots
        #pragma unroll 4
        for (int c = 0; c < 16; c++) {
            asm volatile("cp.async.wait_group 5;" ::: "memory");
            __syncwarp();
            issueC(c + 6);
            uint32_t sA = sbase + A_OFF + (uint32_t)((c & 7) * ASTG);
            uint32_t a[4];
            ldsm_x4(sA + aRow + aCol, a[0], a[1], a[2], a[3]);
            #pragma unroll
            for (int slot = 0; slot < 2; slot++) {
                uint32_t sW = sbase + (uint32_t)(c + slot * 16) * 5120;
                uint32_t bb[5][2];
                ldsm_x4(sW + bRow0 + gbCol, bb[0][0], bb[0][1], bb[1][0], bb[1][1]);
                ldsm_x4(sW + bRow1 + gbCol, bb[2][0], bb[2][1], bb[3][0], bb[3][1]);
                ldsm_x2(sW + bRow2 + gbCol, bb[4][0], bb[4][1]);
                #pragma unroll
                for (int g = 0; g < 5; g++) mma16816(acc[g], a, bb[g]);
            }
        }
        // lo phase: chunks 16..31 (A-lo), hi W slot only
        #pragma unroll 4
        for (int c = 16; c < 32; c++) {
            asm volatile("cp.async.wait_group 5;" ::: "memory");
            __syncwarp();
            issueC(c + 6);
            uint32_t sA = sbase + A_OFF + (uint32_t)((c & 7) * ASTG);
            uint32_t a[4];
            ldsm_x4(sA + aRow + aCol, a[0], a[1], a[2], a[3]);
            uint32_t sW = sbase + (uint32_t)(c - 16) * 5120;
            uint32_t bb[5][2];
            ldsm_x4(sW + bRow0 + gbCol, bb[0][0], bb[0][1], bb[1][0], bb[1][1]);
            ldsm_x4(sW + bRow1 + gbCol, bb[2][0], bb[2][1], bb[3][0], bb[3][1]);
            ldsm_x2(sW + bRow2 + gbCol, bb[4][0], bb[4][1]);
            #pragma unroll
            for (int g = 0; g < 5; g++) mma16816(acc[g], a, bb[g]);
        }
        asm volatile("cp.async.wait_group 0;" ::: "memory");  // drain (empties)
        __syncthreads();

        // ps reduction into (overlaid) smem: 4 k-parts
        {
            float* pb = ps_s + kq * (64 * PS_PAD);
            int rr = mt * 16 + (lane >> 2);
            #pragma unroll
            for (int g = 0; g < 5; g++) {
                int cc = g * 8 + (lane & 3) * 2;
                pb[rr * PS_PAD + cc] = acc[g][0];
                pb[rr * PS_PAD + cc + 1] = acc[g][1];
                pb[(rr + 8) * PS_PAD + cc] = acc[g][2];
                pb[(rr + 8) * PS_PAD + cc + 1] = acc[g][3];
            }
        }
        __syncthreads();

        // gate phase: warps 0-7; warp wg owns hidden column j; lanes own rows
        if (wid < 8) {
            float a0[5], a1[5];
            #pragma unroll
            for (int g = 0; g < 5; g++) {
                int cc = g * 8 + wg;
                float s0 = bias[g], s1 = bias[g];
                #pragma unroll
                for (int kp = 0; kp < 4; kp++) {
                    s0 += ps_s[kp * (64 * PS_PAD) + r0 * PS_PAD + cc];
                    s1 += ps_s[kp * (64 * PS_PAD) + r1 * PS_PAD + cc];
                }
                a0[g] = s0; a1[g] = s1;
            }
            {
                float ig = sigf(p0[0] + a0[0]), fg = sigf(p0[1] + a0[1]);
                float mi = tanhf(p0[2] + a0[2]), og = sigf(p0[3] + a0[3]);
                float cn = ig * mi + fg * c0;
                float o = og * tanhf(cn);
                float hg = sigf(p0[4] + a0[4]);
                o = hg * o + (1.f - hg) * p0[5];
                bool v = (t < len0);
                if (v) { c0 = cn; h0 = o; }
                ystg[r0 * 8 + wg] = v ? o : 0.f;
            }
            {
                float ig = sigf(p1[0] + a1[0]), fg = sigf(p1[1] + a1[1]);
                float mi = tanhf(p1[2] + a1[2]), og = sigf(p1[3] + a1[3]);
                float cn = ig * mi + fg * c1;
                float o = og * tanhf(cn);
                float hg = sigf(p1[4] + a1[4]);
                o = hg * o + (1.f - hg) * p1[5];
                bool v = (t < len1);
                if (v) { c1 = cn; h1 = o; }
                ystg[r1 * 8 + wg] = v ? o : 0.f;
            }
            #pragma unroll
            for (int q = 0; q < 2; q++) {
                float hv = q ? h1 : h0;
                int b = q ? r1 : r0;
                __nv_bfloat16 hi = __float2bfloat16(hv);
                __nv_bfloat16 lo = __float2bfloat16(hv - __bfloat162float(hi));
                hstg[b * 8 + wg] = hi;
                hstg[512 + b * 8 + wg] = lo;
            }
        }
        __syncthreads();

        // coalesced publish: h split (16B per row) + y (two 16B per row)
        __nv_bfloat16* Aw = g_Ah[(t + 1) & 1];
        if (tid < 128) {
            int q = tid >> 6, b = tid & 63;
            uint4 v = *(uint4*)&hstg[q * 512 + b * 8];
            size_t off = (size_t)(q * 16 + cj) * 4096 + b * 64 + ((kxor ^ (b & 7)) << 3);
            *(uint4*)(Aw + off) = v;
        } else if (tid < 256) {
            int hb = (tid - 128) >> 6, b = tid & 63;
            float4 v = *(float4*)&ystg[b * 8 + hb * 4];
            *(float4*)(y + ((size_t)b * TT + t) * HH + jb * 8 + hb * 4) = v;
        }

        grid_barrier(++ep, jb);
    }

    if (wid < 8) {
        outh[(size_t)r0 * HH + j] = h0;
        outh[(size_t)r1 * HH + j] = h1;
        outc[(size_t)r0 * HH + j] = c0;
        outc[(size_t)r1 * HH + j] = c1;
    }
}

extern "C" void kernel_launch(void* const* d_in, const int* in_sizes, int n_in,
                              void* d_out, int out_size)
{
    (void)in_sizes; (void)n_in; (void)out_size;
    const float* x   = (const float*)d_in[0];
    const int*   len = (const int*)d_in[1];
    const float* Wi0 = (const float*)d_in[2];
    const float* Ws0 = (const float*)d_in[3];
    const float* bs0 = (const float*)d_in[4];
    const float* Wi1 = (const float*)d_in[5];
    const float* Ws1 = (const float*)d_in[6];
    const float* bs1 = (const float*)d_in[7];
    float* out = (float*)d_out;

    float* y0_ptr = nullptr;
    cudaGetSymbolAddress((void**)&y0_ptr, g_y0);
    __nv_bfloat16* abf = nullptr; cudaGetSymbolAddress((void**)&abf, g_Abf);
    __nv_bfloat16* bbf = nullptr; cudaGetSymbolAddress((void**)&bbf, g_Bbf);

    cudaFuncSetAttribute(gemm_mma, cudaFuncAttributeMaxDynamicSharedMemorySize, SMEM_GEMM);
    cudaFuncSetAttribute(rec_kernel, cudaFuncAttributeMaxDynamicSharedMemorySize, SMEM_REC);

    float* outh = out + BTH;
    float* outc = out + BTH + 2 * BH;

    dim3 ggrid(SIXH / GNT, (BB * TT) / GMT);
    dim3 cbgrid(SIXH / 32, 1024 / 32);
    const int convA_blocks = (int)(((size_t)32768 * 512) / 256);
    const int packw_blocks = (int)((128ull * 32 * 40 * 64) / 256);

    // ---- layer 0 ----
    packw_kernel<<<packw_blocks, 256>>>(Ws0);
    convA_kernel<<<convA_blocks, 256>>>(x, abf);
    convB_kernel<<<cbgrid, 256>>>(Wi0, bbf);
    gemm_mma<<<ggrid, 512, SMEM_GEMM>>>(abf, bbf);
    rec_kernel<<<NBLK, 512, SMEM_REC>>>(bs0, len, y0_ptr, outh, outc);

    // ---- layer 1 ----
    packw_kernel<<<packw_blocks, 256>>>(Ws1);
    convA_kernel<<<convA_blocks, 256>>>(y0_ptr, abf);
    convB_kernel<<<cbgrid, 256>>>(Wi1, bbf);
    gemm_mma<<<ggrid, 512, SMEM_GEMM>>>(abf, bbf);
    rec_kernel<<<NBLK, 512, SMEM_REC>>>(bs1, len, out, outh + BH, outc + BH);
}

// round 17
// speedup vs baseline: 1.1923x; 1.1923x over previous
#include <cuda_runtime.h>
#include <cuda_bf16.h>
#include <cuda_fp16.h>
#include <cstdint>
#include <math.h>

#define BB 64
#define TT 512
#define DD 1024
#define HH 1024
#define SIXH (6 * HH)
#define FIVEH (5 * HH)
#define BTH (BB * TT * HH)
#define BH (BB * HH)

#define NBLK 128

// input-projection GEMM (unchanged, bf16 3-term)
#define GK 3072
#define GKC 64
#define GNCHUNK (GK / GKC)
#define GMT 128
#define GNT 256
#define GSTAGE 49152
#define SMEM_GEMM (2 * GSTAGE)

// recurrent kernel (fp16 2-term): W resident 160KB; A ring 8 x 8KB = 64KB.
// ps/hstg/ystg overlay the A ring (used only after the chunk loop).
#define ASTG 8192
#define WSM 163840
#define A_OFF WSM
#define PS_PAD 42
#define HSTG_OFF (A_OFF + 4 * 64 * PS_PAD * 4)   // A_OFF + 43008
#define YSTG_OFF (HSTG_OFF + 1024)
#define SMEM_REC (WSM + 8 * ASTG)                // 229376 (224KB)

__device__ __align__(16) float g_pi[201326592];
__device__ __align__(16) float g_y0[BTH];
__device__ __align__(16) __nv_bfloat16 g_Abf[98304ull * 1024ull];
__device__ __align__(16) __nv_bfloat16 g_Bbf[6144ull * 3072ull];
__device__ __align__(128) __half g_Wr[128ull * 32ull * 2560ull];   // fp16 Whi|Wlo pack
__device__ __align__(128) __half g_Ah[2][65536];                   // h fp16, swizzled chunks

// hierarchical grid barrier state (monotonic counters; replay-safe)
__device__ unsigned g_cnt[8];
__device__ unsigned g_cntm;
__device__ unsigned g_rel;

__device__ __forceinline__ float sigf(float x) { return 1.f / (1.f + expf(-x)); }

__device__ __forceinline__ uint32_t smem_u32(const void* p) {
    uint32_t a;
    asm("{ .reg .u64 t; cvta.to.shared.u64 t, %1; cvt.u32.u64 %0, t; }" : "=r"(a) : "l"(p));
    return a;
}
__device__ __forceinline__ void cp_async16(uint32_t d, const void* g) {
    asm volatile("cp.async.cg.shared.global [%0], [%1], 16;" :: "r"(d), "l"(g));
}
__device__ __forceinline__ void ldsm_x4(uint32_t addr, uint32_t& r0, uint32_t& r1,
                                        uint32_t& r2, uint32_t& r3) {
    asm volatile("ldmatrix.sync.aligned.m8n8.x4.shared.b16 {%0,%1,%2,%3}, [%4];"
                 : "=r"(r0), "=r"(r1), "=r"(r2), "=r"(r3) : "r"(addr));
}
__device__ __forceinline__ void ldsm_x2(uint32_t addr, uint32_t& r0, uint32_t& r1) {
    asm volatile("ldmatrix.sync.aligned.m8n8.x2.shared.b16 {%0,%1}, [%2];"
                 : "=r"(r0), "=r"(r1) : "r"(addr));
}
__device__ __forceinline__ void mma16816(float* c, const uint32_t* a, const uint32_t* b) {
    asm volatile("mma.sync.aligned.m16n8k16.row.col.f32.bf16.bf16.f32 "
                 "{%0,%1,%2,%3}, {%4,%5,%6,%7}, {%8,%9}, {%0,%1,%2,%3};"
                 : "+f"(c[0]), "+f"(c[1]), "+f"(c[2]), "+f"(c[3])
                 : "r"(a[0]), "r"(a[1]), "r"(a[2]), "r"(a[3]), "r"(b[0]), "r"(b[1]));
}
__device__ __forceinline__ void mma16816h(float* c, const uint32_t* a, const uint32_t* b) {
    asm volatile("mma.sync.aligned.m16n8k16.row.col.f32.f16.f16.f32 "
                 "{%0,%1,%2,%3}, {%4,%5,%6,%7}, {%8,%9}, {%0,%1,%2,%3};"
                 : "+f"(c[0]), "+f"(c[1]), "+f"(c[2]), "+f"(c[3])
                 : "r"(a[0]), "r"(a[1]), "r"(a[2]), "r"(a[3]), "r"(b[0]), "r"(b[1]));
}

// hierarchical epoch barrier: 8 group counters -> master -> release word
__device__ __forceinline__ void grid_barrier(unsigned ep, int jb) {
    __syncthreads();
    if (threadIdx.x == 0) {
        __threadfence();
        unsigned v = atomicAdd(&g_cnt[jb & 7], 1u) + 1u;
        if (v == ep * 16u) {
            unsigned m = atomicAdd(&g_cntm, 1u) + 1u;
            if (m == ep * 8u) {
                atomicExch(&g_rel, ep);
            }
        }
        while (*(volatile unsigned*)&g_rel < ep) { }
    }
    __syncthreads();
}

// ---------------------------------------------------------------------------
__global__ void convA_kernel(const float* __restrict__ src, __nv_bfloat16* __restrict__ dst) {
    size_t i = (size_t)blockIdx.x * blockDim.x + threadIdx.x;
    int m = (int)(i >> 9), r = (int)(i & 511);
    float2 a = ((const float2*)src)[i];
    __nv_bfloat162 hi, lo;
    hi.x = __float2bfloat16(a.x); hi.y = __float2bfloat16(a.y);
    lo.x = __float2bfloat16(a.x - __bfloat162float(hi.x));
    lo.y = __float2bfloat16(a.y - __bfloat162float(hi.y));
    __nv_bfloat162* d = (__nv_bfloat162*)dst + (size_t)m * 1536;
    d[r] = hi; d[512 + r] = lo; d[1024 + r] = hi;
}

__global__ void convB_kernel(const float* __restrict__ W, __nv_bfloat16* __restrict__ dst) {
    __shared__ float t[32][33];
    int nb = blockIdx.x * 32, kb = blockIdx.y * 32;
    int tx = threadIdx.x & 31, ty = threadIdx.x >> 5;
    #pragma unroll
    for (int i = 0; i < 4; i++)
        t[ty + i * 8][tx] = W[(size_t)(kb + ty + i * 8) * SIXH + nb + tx];
    __syncthreads();
    #pragma unroll
    for (int i = 0; i < 4; i++) {
        int ny = ty + i * 8;
        float a = t[tx][ny];
        __nv_bfloat16 hi = __float2bfloat16(a);
        __nv_bfloat16 lo = __float2bfloat16(a - __bfloat162float(hi));
        __nv_bfloat16* dr = dst + (size_t)(nb + ny) * GK;
        dr[kb + tx] = hi; dr[1024 + kb + tx] = hi; dr[2048 + kb + tx] = lo;
    }
}

// ---------------------------------------------------------------------------
__global__ void __launch_bounds__(512, 1) gemm_mma(const __nv_bfloat16* __restrict__ A,
                                                   const __nv_bfloat16* __restrict__ B) {
    extern __shared__ __align__(1024) char sm[];
    const uint32_t sbase = smem_u32(sm);
    const int tid = threadIdx.x, wid = tid >> 5, lane = tid & 31;
    const int n0 = blockIdx.x * GNT, m0 = blockIdx.y * GMT;
    const int m_warp = (wid & 1) * 64;
    const int n_warp = (wid >> 1) * 32;

    const int ahalf = lane >> 4;
    const int bhalf = (lane >> 3) & 1;
    int aoff[4], a7[4], boff[2], b7[2];
    #pragma unroll
    for (int mt = 0; mt < 4; mt++) {
        int r = m_warp + mt * 16 + (lane & 15);
        aoff[mt] = r * 128; a7[mt] = r & 7;
    }
    #pragma unroll
    for (int bt = 0; bt < 2; bt++) {
        int r = n_warp + bt * 16 + (lane & 7) + ((lane >> 4) << 3);
        boff[bt] = r * 128; b7[bt] = r & 7;
    }

    float acc[4][4][4];
    #pragma unroll
    for (int i = 0; i < 4; i++)
        #pragma unroll
        for (int j = 0; j < 4; j++)
            #pragma unroll
            for (int k = 0; k < 4; k++) acc[i][j][k] = 0.f;

    auto load_chunk = [&](int kc, int buf) {
        uint32_t sa = sbase + buf * GSTAGE;
        uint32_t sb = sa + 16384;
        const char* ga = (const char*)(A + (size_t)m0 * GK + kc * GKC);
        const char* gb = (const char*)(B + (size_t)n0 * GK + kc * GKC);
        #pragma unroll
        for (int i = 0; i < 2; i++) {
            int idx = tid + i * 512, r = idx >> 3, c = idx & 7;
            cp_async16(sa + r * 128 + (((c ^ (r & 7)) << 4)), ga + (size_t)r * (GK * 2) + c * 16);
        }
        #pragma unroll
        for (int i = 0; i < 4; i++) {
            int idx = tid + i * 512, r = idx >> 3, c = idx & 7;
            cp_async16(sb + r * 128 + (((c ^ (r & 7)) << 4)), gb + (size_t)r * (GK * 2) + c * 16);
        }
        asm volatile("cp.async.commit_group;" ::: "memory");
    };

    load_chunk(0, 0);
    for (int kc = 0; kc < GNCHUNK; kc++) {
        int buf = kc & 1;
        if (kc + 1 < GNCHUNK) {
            load_chunk(kc + 1, buf ^ 1);
            asm volatile("cp.async.wait_group 1;" ::: "memory");
        } else {
            asm volatile("cp.async.wait_group 0;" ::: "memory");
        }
        __syncthreads();

        uint32_t saA = sbase + buf * GSTAGE;
        uint32_t saB = saA + 16384;
        #pragma unroll
        for (int ks = 0; ks < 4; ks++) {
            uint32_t a[4][4], b[4][2];
            #pragma unroll
            for (int mt = 0; mt < 4; mt++) {
                uint32_t addr = saA + aoff[mt] + ((((ks << 1) + ahalf) ^ a7[mt]) << 4);
                ldsm_x4(addr, a[mt][0], a[mt][1], a[mt][2], a[mt][3]);
            }
            #pragma unroll
            for (int bt = 0; bt < 2; bt++) {
                uint32_t addr = saB + boff[bt] + ((((ks << 1) + bhalf) ^ b7[bt]) << 4);
                ldsm_x4(addr, b[2 * bt][0], b[2 * bt][1], b[2 * bt + 1][0], b[2 * bt + 1][1]);
            }
            #pragma unroll
            for (int mt = 0; mt < 4; mt++)
                #pragma unroll
                for (int nt = 0; nt < 4; nt++)
                    mma16816(acc[mt][nt], a[mt], b[nt]);
        }
        __syncthreads();
    }

    #pragma unroll
    for (int mt = 0; mt < 4; mt++) {
        int m = m0 + m_warp + mt * 16 + (lane >> 2);
        #pragma unroll
        for (int nt = 0; nt < 4; nt++) {
            int n = n0 + n_warp + nt * 8 + (lane & 3) * 2;
            *(float2*)(g_pi + (size_t)m * SIXH + n) = make_float2(acc[mt][nt][0], acc[mt][nt][1]);
            *(float2*)(g_pi + (size_t)(m + 8) * SIXH + n) = make_float2(acc[mt][nt][2], acc[mt][nt][3]);
        }
    }
}

// ---------------------------------------------------------------------------
// Pack recurrent weights in fp16 2-term: chunks 0..15 = Whi, 16..31 = Wlo.
// ---------------------------------------------------------------------------
__global__ void packw_kernel(const float* __restrict__ Ws) {
    size_t idx = (size_t)blockIdx.x * blockDim.x + threadIdx.x;
    if (idx >= 128ull * 32 * 40 * 64) return;
    int kk = (int)(idx & 63); size_t r = idx >> 6;
    int nn = (int)(r % 40); r /= 40;
    int wc = (int)(r & 31); int jb = (int)(r >> 5);
    int g = nn >> 3, jj = jb * 8 + (nn & 7);
    int k = (wc & 15) * 64 + kk;
    float v = Ws[(size_t)k * FIVEH + g * HH + jj];
    __half hi = __float2half(v);
    __half o = (wc < 16) ? hi : __float2half(v - __half2float(hi));
    size_t off = ((size_t)(jb * 32 + wc)) * 2560 + nn * 64 + (((kk >> 3) ^ (nn & 7)) << 3) + (kk & 7);
    g_Wr[off] = o;
}

// ---------------------------------------------------------------------------
// Persistent recurrent kernel (fp16 2-term): 512 threads, 16 warps =
// 4 m-tiles x 4 k-quarters. W resident; 16 A chunks/step in 8-slot ring.
// ---------------------------------------------------------------------------
__global__ void __launch_bounds__(512, 1) rec_kernel(
    const float* __restrict__ bs, const int* __restrict__ lengths,
    float* __restrict__ y, float* __restrict__ outh, float* __restrict__ outc)
{
    extern __shared__ __align__(1024) char sm[];
    __shared__ unsigned s_base;
    const uint32_t sbase = smem_u32(sm);
    float* ps_s = (float*)(sm + A_OFF);                 // 4 x 64 x PS_PAD (overlay)
    __half* hstg = (__half*)(sm + HSTG_OFF);            // [64][8]
    float* ystg = (float*)(sm + YSTG_OFF);              // [64][8]

    const int tid = threadIdx.x, wid = tid >> 5, lane = tid & 31;
    const int jb = blockIdx.x;
    const int mt = wid & 3, kq = wid >> 2;
    const int wg = wid & 7;
    const int j = jb * 8 + wg;
    const int r0 = lane, r1 = lane + 32;
    const int cj = jb >> 3, u8 = jb & 7;

    const char* Wbase = (const char*)(g_Wr + (size_t)jb * 32 * 2560);

    if (tid == 0) s_base = *(volatile unsigned*)&g_rel;

    // resident W load: 160KB via cp.async from all threads
    #pragma unroll 4
    for (int i = 0; i < 20; i++) {
        int uu = tid + i * 512;
        cp_async16(sbase + uu * 16, Wbase + (size_t)uu * 16);
    }
    asm volatile("cp.async.commit_group;" ::: "memory");

    // zero A' buffer 0 (initial h = 0): 8192 uint4 over 128 blocks = 64/block
    if (tid < 64) ((uint4*)g_Ah)[jb * 64 + tid] = make_uint4(0, 0, 0, 0);

    const int len0 = lengths[r0], len1 = lengths[r1];
    float bias[5];
    #pragma unroll
    for (int g = 0; g < 5; g++) bias[g] = (wid < 8) ? bs[g * HH + j] : 0.f;

    asm volatile("cp.async.wait_group 0;" ::: "memory");
    __syncthreads();
    unsigned ep = s_base;
    grid_barrier(++ep, jb);

    const int sw = lane & 7;
    const uint32_t aRow = (uint32_t)((mt * 16 + (lane & 15)) * 128);
    const int ah = lane >> 4;
    const uint32_t bRow0 = (uint32_t)((((lane & 7) + ((lane >> 4) << 3))) * 128);
    const uint32_t bRow1 = bRow0 + 16 * 128;
    const uint32_t bRow2 = (uint32_t)((32 + (lane & 7)) * 128);
    const int bh = (lane >> 3) & 1;
    const int gg = kq * 2;
    const uint32_t aCol = (uint32_t)(((gg + ah) ^ sw) << 4);
    const uint32_t gbCol = (uint32_t)(((gg + bh) ^ sw) << 4);
    const uint32_t adst = sbase + A_OFF + (uint32_t)(tid << 4);

    float h0 = 0.f, h1 = 0.f, c0 = 0.f, c1 = 0.f;

    for (int t = 0; t < TT; t++) {
        const char* Abase = (const char*)(g_Ah[t & 1]) + (tid << 4);

        // batch = 2 chunks of 8KB; 8-slot ring; always-commit
        auto issueB = [&](int b) {
            if (b < 8) {
                #pragma unroll
                for (int q = 0; q < 2; q++) {
                    int c = 2 * b + q;
                    cp_async16(adst + (uint32_t)((c & 7) * ASTG), Abase + (size_t)c * ASTG);
                }
            }
            asm volatile("cp.async.commit_group;" ::: "memory");
        };
        issueB(0); issueB(1); issueB(2);

        float p0[6], p1[6];
        if (wid < 8) {
            const float* pr0 = g_pi + ((size_t)r0 * TT + t) * SIXH + j;
            const float* pr1 = g_pi + ((size_t)r1 * TT + t) * SIXH + j;
            #pragma unroll
            for (int g = 0; g < 6; g++) { p0[g] = pr0[g * HH]; p1[g] = pr1[g * HH]; }
        }

        float acc[5][4];
        #pragma unroll
        for (int g = 0; g < 5; g++)
            #pragma unroll
            for (int q = 0; q < 4; q++) acc[g][q] = 0.f;

        // 16 chunks, each vs Whi (slot 0) and Wlo (slot 1)
        for (int b = 0; b < 8; b++) {
            asm volatile("cp.async.wait_group 2;" ::: "memory");
            __syncthreads();
            issueB(b + 3);
            #pragma unroll
            for (int q = 0; q < 2; q++) {
                int c = 2 * b + q;
                uint32_t sA = sbase + A_OFF + (uint32_t)((c & 7) * ASTG);
                uint32_t a[4];
                ldsm_x4(sA + aRow + aCol, a[0], a[1], a[2], a[3]);
                #pragma unroll
                for (int slot = 0; slot < 2; slot++) {
                    uint32_t sW = sbase + (uint32_t)(c + slot * 16) * 5120;
                    uint32_t bb[5][2];
                    ldsm_x4(sW + bRow0 + gbCol, bb[0][0], bb[0][1], bb[1][0], bb[1][1]);
                    ldsm_x4(sW + bRow1 + gbCol, bb[2][0], bb[2][1], bb[3][0], bb[3][1]);
                    ldsm_x2(sW + bRow2 + gbCol, bb[4][0], bb[4][1]);
                    #pragma unroll
                    for (int g = 0; g < 5; g++) mma16816h(acc[g], a, bb[g]);
                }
            }
        }
        __syncthreads();

        // ps reduction into (overlaid) smem: 4 k-parts
        {
            float* pb = ps_s + kq * (64 * PS_PAD);
            int rr = mt * 16 + (lane >> 2);
            #pragma unroll
            for (int g = 0; g < 5; g++) {
                int cc = g * 8 + (lane & 3) * 2;
                pb[rr * PS_PAD + cc] = acc[g][0];
                pb[rr * PS_PAD + cc + 1] = acc[g][1];
                pb[(rr + 8) * PS_PAD + cc] = acc[g][2];
                pb[(rr + 8) * PS_PAD + cc + 1] = acc[g][3];
            }
        }
        __syncthreads();

        // gate phase: warps 0-7; warp wg owns hidden column j; lanes own rows
        if (wid < 8) {
            float a0[5], a1[5];
            #pragma unroll
            for (int g = 0; g < 5; g++) {
                int cc = g * 8 + wg;
                float s0 = bias[g], s1 = bias[g];
                #pragma unroll
                for (int kp = 0; kp < 4; kp++) {
                    s0 += ps_s[kp * (64 * PS_PAD) + r0 * PS_PAD + cc];
                    s1 += ps_s[kp * (64 * PS_PAD) + r1 * PS_PAD + cc];
                }
                a0[g] = s0; a1[g] = s1;
            }
            {
                float ig = sigf(p0[0] + a0[0]), fg = sigf(p0[1] + a0[1]);
                float mi = tanhf(p0[2] + a0[2]), og = sigf(p0[3] + a0[3]);
                float cn = ig * mi + fg * c0;
                float o = og * tanhf(cn);
                float hg = sigf(p0[4] + a0[4]);
                o = hg * o + (1.f - hg) * p0[5];
                bool v = (t < len0);
                if (v) { c0 = cn; h0 = o; }
                ystg[r0 * 8 + wg] = v ? o : 0.f;
            }
            {
                float ig = sigf(p1[0] + a1[0]), fg = sigf(p1[1] + a1[1]);
                float mi = tanhf(p1[2] + a1[2]), og = sigf(p1[3] + a1[3]);
                float cn = ig * mi + fg * c1;
                float o = og * tanhf(cn);
                float hg = sigf(p1[4] + a1[4]);
                o = hg * o + (1.f - hg) * p1[5];
                bool v = (t < len1);
                if (v) { c1 = cn; h1 = o; }
                ystg[r1 * 8 + wg] = v ? o : 0.f;
            }
            hstg[r0 * 8 + wg] = __float2half(h0);
            hstg[r1 * 8 + wg] = __float2half(h1);
        }
        __syncthreads();

        // coalesced publish: h (16B per row) + y (two 16B per row)
        char* Aw = (char*)(g_Ah[(t + 1) & 1]);
        if (tid < 64) {
            int b = tid;
            uint4 v = *(uint4*)&hstg[b * 8];
            size_t off = (size_t)cj * 8192 + b * 128 + ((u8 ^ (b & 7)) << 4);
            *(uint4*)(Aw + off) = v;
        } else if (tid < 192) {
            int hb = (tid - 64) >> 6, b = (tid - 64) & 63;
            float4 v = *(float4*)&ystg[b * 8 + hb * 4];
            *(float4*)(y + ((size_t)b * TT + t) * HH + jb * 8 + hb * 4) = v;
        }

        grid_barrier(++ep, jb);
    }

    if (wid < 8) {
        outh[(size_t)r0 * HH + j] = h0;
        outh[(size_t)r1 * HH + j] = h1;
        outc[(size_t)r0 * HH + j] = c0;
        outc[(size_t)r1 * HH + j] = c1;
    }
}

extern "C" void kernel_launch(void* const* d_in, const int* in_sizes, int n_in,
                              void* d_out, int out_size)
{
    (void)in_sizes; (void)n_in; (void)out_size;
    const float* x   = (const float*)d_in[0];
    const int*   len = (const int*)d_in[1];
    const float* Wi0 = (const float*)d_in[2];
    const float* Ws0 = (const float*)d_in[3];
    const float* bs0 = (const float*)d_in[4];
    const float* Wi1 = (const float*)d_in[5];
    const float* Ws1 = (const float*)d_in[6];
    const float* bs1 = (const float*)d_in[7];
    float* out = (float*)d_out;

    float* y0_ptr = nullptr;
    cudaGetSymbolAddress((void**)&y0_ptr, g_y0);
    __nv_bfloat16* abf = nullptr; cudaGetSymbolAddress((void**)&abf, g_Abf);
    __nv_bfloat16* bbf = nullptr; cudaGetSymbolAddress((void**)&bbf, g_Bbf);

    cudaFuncSetAttribute(gemm_mma, cudaFuncAttributeMaxDynamicSharedMemorySize, SMEM_GEMM);
    cudaFuncSetAttribute(rec_kernel, cudaFuncAttributeMaxDynamicSharedMemorySize, SMEM_REC);

    float* outh = out + BTH;
    float* outc = out + BTH + 2 * BH;

    dim3 ggrid(SIXH / GNT, (BB * TT) / GMT);
    dim3 cbgrid(SIXH / 32, 1024 / 32);
    const int convA_blocks = (int)(((size_t)32768 * 512) / 256);
    const int packw_blocks = (int)((128ull * 32 * 40 * 64) / 256);

    // ---- layer 0 ----
    packw_kernel<<<packw_blocks, 256>>>(Ws0);
    convA_kernel<<<convA_blocks, 256>>>(x, abf);
    convB_kernel<<<cbgrid, 256>>>(Wi0, bbf);
    gemm_mma<<<ggrid, 512, SMEM_GEMM>>>(abf, bbf);
    rec_kernel<<<NBLK, 512, SMEM_REC>>>(bs0, len, y0_ptr, outh, outc);

    // ---- layer 1 ----
    packw_kernel<<<packw_blocks, 256>>>(Ws1);
    convA_kernel<<<convA_blocks, 256>>>(y0_ptr, abf);
    convB_kernel<<<cbgrid, 256>>>(Wi1, bbf);
    gemm_mma<<<ggrid, 512, SMEM_GEMM>>>(abf, bbf);
    rec_kernel<<<NBLK, 512, SMEM_REC>>>(bs1, len, out, outh + BH, outc + BH);
}